// round 4
// baseline (speedup 1.0000x reference)
#include <cuda_runtime.h>

#define N_NODES 100000
#define N_EDGES 1600000
// layer dims: F_IN=128, HID=64, N_CLS=40

// Scratch (device globals: allocation-free, graph-safe)
__device__ __align__(16) float g_y1[N_NODES * 128];   // [x@W1_l | x@W1_r]
__device__ __align__(16) float g_agg1[N_NODES * 64];  // edge-summed y1_l
__device__ __align__(16) float g_h[N_NODES * 64];     // relu output
__device__ __align__(16) float g_y2[N_NODES * 80];    // [h@W2_l | h@W2_r]
__device__ __align__(16) float g_agg2[N_NODES * 40];  // edge-summed y2_l
__device__ __align__(16) float g_cnt[N_NODES];        // in-degree

__device__ __forceinline__ void red_add_v4(float* p, float4 v) {
    atomicAdd(p + 0, v.x);
    atomicAdd(p + 1, v.y);
    atomicAdd(p + 2, v.z);
    atomicAdd(p + 3, v.w);
}

// ---------------------------------------------------------------- zero
__global__ void zero_kernel() {
    int i = blockIdx.x * blockDim.x + threadIdx.x;
    const int A1 = N_NODES * 64;       // agg1
    const int A2 = A1 + N_NODES * 40;  // agg2
    const int A3 = A2 + N_NODES;       // cnt
    if (i >= A3) return;
    if (i < A1)       g_agg1[i] = 0.0f;
    else if (i < A2)  g_agg2[i - A1] = 0.0f;
    else              g_cnt[i - A2] = 0.0f;
}

// ---------------------------------------------------------------- GEMM1
// y1[n][0:64]  = x[n] @ W1_l   (l-part, to be edge-aggregated)
// y1[n][64:128]= x[n] @ W1_r   (self-part)
// BM=64 nodes, BN=128 cols, K=128. 256 threads, TM=8 x TN=4 register tile.
__global__ void gemm1_kernel(const float* __restrict__ x,
                             const float* __restrict__ Wl,
                             const float* __restrict__ Wr) {
    __shared__ float As[64][128];  // 32 KB
    const int bm = blockIdx.x * 64;
    const int t  = threadIdx.x;

    for (int i = t; i < 64 * 32; i += 256) {
        int m = i >> 5, k4 = i & 31;
        int gm = bm + m;
        float4 v = make_float4(0.f, 0.f, 0.f, 0.f);
        if (gm < N_NODES) v = __ldg((const float4*)x + gm * 32 + k4);
        *(float4*)&As[m][k4 * 4] = v;
    }
    __syncthreads();

    const int ng = t & 31, mg = t >> 5;
    const int n0 = ng * 4, m0 = mg * 8;
    // column n0: first 64 cols come from W1_l, next 64 from W1_r (both [128][64] row-major)
    const float* B = (n0 < 64) ? (Wl + n0) : (Wr + (n0 - 64));

    float acc[8][4];
    #pragma unroll
    for (int i = 0; i < 8; i++)
        { acc[i][0] = 0.f; acc[i][1] = 0.f; acc[i][2] = 0.f; acc[i][3] = 0.f; }

    #pragma unroll 4
    for (int k = 0; k < 128; k++) {
        float4 b = __ldg((const float4*)(B + k * 64));
        #pragma unroll
        for (int i = 0; i < 8; i++) {
            float a = As[m0 + i][k];  // same addr across warp: broadcast
            acc[i][0] += a * b.x; acc[i][1] += a * b.y;
            acc[i][2] += a * b.z; acc[i][3] += a * b.w;
        }
    }

    #pragma unroll
    for (int i = 0; i < 8; i++) {
        int gm = bm + m0 + i;
        if (gm < N_NODES)
            *(float4*)&g_y1[gm * 128 + n0] =
                make_float4(acc[i][0], acc[i][1], acc[i][2], acc[i][3]);
    }
}

// ---------------------------------------------------------------- edge pass 1
// edge_index is INT32, shape [2, E]: row 0 = src, row 1 = dst.
// one thread per (edge, float4-chunk); 16 chunks cover the 64-f l-part
__global__ void edge1_kernel(const int* __restrict__ ei) {
    int i = blockIdx.x * blockDim.x + threadIdx.x;
    if (i >= N_EDGES * 16) return;
    int e = i >> 4, j = i & 15;
    int s = __ldg(ei + e);
    int d = __ldg(ei + N_EDGES + e);
    float4 v = __ldg((const float4*)g_y1 + s * 32 + j);  // y1 row = 32 float4, first 16 = l-part
    red_add_v4(&g_agg1[d * 64 + j * 4], v);
    if (j == 0) atomicAdd(&g_cnt[d], 1.0f);
}

// ---------------------------------------------------------------- normalize + bias + relu
__global__ void act1_kernel(const float* __restrict__ b1) {
    int i = blockIdx.x * blockDim.x + threadIdx.x;
    if (i >= N_NODES * 64) return;
    int n = i >> 6, j = i & 63;
    float c = fmaxf(g_cnt[n], 1.0f);
    float v = g_agg1[i] / c + g_y1[(n << 7) + 64 + j] + __ldg(b1 + j);
    g_h[i] = fmaxf(v, 0.0f);
}

// ---------------------------------------------------------------- GEMM2
// y2[n][0:40] = h[n] @ W2_l ; y2[n][40:80] = h[n] @ W2_r. BM=64, BN=80, K=64.
// 160 threads: 20 col-groups (TN=4) x 8 row-groups (TM=8).
__global__ void gemm2_kernel(const float* __restrict__ Wl,
                             const float* __restrict__ Wr) {
    __shared__ float As[64][64];  // 16 KB
    const int bm = blockIdx.x * 64;
    const int t  = threadIdx.x;

    for (int i = t; i < 64 * 16; i += 160) {
        int m = i >> 4, k4 = i & 15;
        int gm = bm + m;
        float4 v = make_float4(0.f, 0.f, 0.f, 0.f);
        if (gm < N_NODES) v = *((const float4*)g_h + gm * 16 + k4);
        *(float4*)&As[m][k4 * 4] = v;
    }
    __syncthreads();

    const int ng = t % 20, mg = t / 20;
    const int n0 = ng * 4, m0 = mg * 8;
    const float* B = (n0 < 40) ? (Wl + n0) : (Wr + (n0 - 40));  // [64][40] row-major

    float acc[8][4];
    #pragma unroll
    for (int i = 0; i < 8; i++)
        { acc[i][0] = 0.f; acc[i][1] = 0.f; acc[i][2] = 0.f; acc[i][3] = 0.f; }

    #pragma unroll 4
    for (int k = 0; k < 64; k++) {
        float4 b = __ldg((const float4*)(B + k * 40));
        #pragma unroll
        for (int i = 0; i < 8; i++) {
            float a = As[m0 + i][k];
            acc[i][0] += a * b.x; acc[i][1] += a * b.y;
            acc[i][2] += a * b.z; acc[i][3] += a * b.w;
        }
    }

    #pragma unroll
    for (int i = 0; i < 8; i++) {
        int gm = bm + m0 + i;
        if (gm < N_NODES)
            *(float4*)&g_y2[gm * 80 + n0] =
                make_float4(acc[i][0], acc[i][1], acc[i][2], acc[i][3]);
    }
}

// ---------------------------------------------------------------- edge pass 2
// one thread per (edge, float4-chunk); 10 chunks cover the 40-f z-part
__global__ void edge2_kernel(const int* __restrict__ ei) {
    int i = blockIdx.x * blockDim.x + threadIdx.x;
    if (i >= N_EDGES * 10) return;
    int e = i / 10, j = i - e * 10;
    int s = __ldg(ei + e);
    int d = __ldg(ei + N_EDGES + e);
    float4 v = __ldg((const float4*)g_y2 + s * 20 + j);  // y2 row = 20 float4, first 10 = z-part
    red_add_v4(&g_agg2[d * 40 + j * 4], v);
}

// ---------------------------------------------------------------- final: normalize + bias + log_softmax
// one warp per node; lane covers class lane (0..31) and lane+32 (lanes 0..7)
__global__ void final_kernel(const float* __restrict__ b2, float* __restrict__ out) {
    int gw   = (blockIdx.x * blockDim.x + threadIdx.x) >> 5;
    int lane = threadIdx.x & 31;
    if (gw >= N_NODES) return;
    int n = gw;
    float inv = 1.0f / fmaxf(g_cnt[n], 1.0f);

    int c1 = lane + 32;
    float v0 = g_agg2[n * 40 + lane] * inv + g_y2[n * 80 + 40 + lane] + __ldg(b2 + lane);
    float v1 = -3.0e38f;
    if (c1 < 40)
        v1 = g_agg2[n * 40 + c1] * inv + g_y2[n * 80 + 40 + c1] + __ldg(b2 + c1);

    float m = fmaxf(v0, v1);
    #pragma unroll
    for (int o = 16; o; o >>= 1) m = fmaxf(m, __shfl_xor_sync(0xFFFFFFFFu, m, o));

    float s = expf(v0 - m) + ((c1 < 40) ? expf(v1 - m) : 0.0f);
    #pragma unroll
    for (int o = 16; o; o >>= 1) s += __shfl_xor_sync(0xFFFFFFFFu, s, o);

    float lse = m + logf(s);
    out[n * 40 + lane] = v0 - lse;
    if (c1 < 40) out[n * 40 + c1] = v1 - lse;
}

// ---------------------------------------------------------------- launch
// Inputs resolved BY ELEMENT COUNT (robust to metadata ordering):
//   12800000 -> x ; 3200000 -> edge_index (int32) ; 8192 -> W1_l then W1_r ;
//   64 -> b1 ; 2560 -> W2_l then W2_r ; 40 -> b2.
extern "C" void kernel_launch(void* const* d_in, const int* in_sizes, int n_in,
                              void* d_out, int out_size) {
    const float* x   = 0; const int* ei = 0;
    const float* W1l = 0; const float* W1r = 0; const float* b1 = 0;
    const float* W2l = 0; const float* W2r = 0; const float* b2 = 0;

    for (int i = 0; i < n_in; i++) {
        int sz = in_sizes[i];
        const void* p = d_in[i];
        if      (sz == N_NODES * 128)  x  = (const float*)p;
        else if (sz == 2 * N_EDGES)    ei = (const int*)p;
        else if (sz == 128 * 64) { if (!W1l) W1l = (const float*)p; else W1r = (const float*)p; }
        else if (sz == 64 * 40)  { if (!W2l) W2l = (const float*)p; else W2r = (const float*)p; }
        else if (sz == 64)             b1 = (const float*)p;
        else if (sz == 40)             b2 = (const float*)p;
    }
    float* out = (float*)d_out;

    zero_kernel <<<(N_NODES * 105 + 255) / 256, 256>>>();
    gemm1_kernel<<<(N_NODES + 63) / 64, 256>>>(x, W1l, W1r);
    edge1_kernel<<<(N_EDGES * 16 + 255) / 256, 256>>>(ei);
    act1_kernel <<<(N_NODES * 64 + 255) / 256, 256>>>(b1);
    gemm2_kernel<<<(N_NODES + 63) / 64, 160>>>(W2l, W2r);
    edge2_kernel<<<(N_EDGES * 10 + 255) / 256, 256>>>(ei);
    final_kernel<<<(N_NODES * 32 + 255) / 256, 256>>>(b2, out);
}

// round 5
// speedup vs baseline: 2.0264x; 2.0264x over previous
#include <cuda_runtime.h>

#define N_NODES 100000
#define N_EDGES 1600000
#define NB_SCAN 98            // ceil(100000/1024)
// layer dims: F_IN=128, HID=64, N_CLS=40

// Scratch (device globals: allocation-free, graph-safe)
__device__ __align__(16) float g_y1[N_NODES * 128];   // [x@W1_l | x@W1_r]
__device__ __align__(16) float g_h[N_NODES * 64];     // relu output
__device__ __align__(16) float g_y2[N_NODES * 80];    // [h@W2_l | h@W2_r]
__device__ int g_deg[N_NODES];        // in-degree histogram
__device__ int g_excl[N_NODES];       // block-local exclusive scan
__device__ int g_bsum[NB_SCAN];       // per-block sums
__device__ int g_boff[NB_SCAN];       // scanned block offsets
__device__ int g_ptr[N_NODES + 1];    // CSR row pointers (by dst)
__device__ int g_pos[N_NODES];        // scatter cursors
__device__ int g_csr[N_EDGES];        // src ids grouped by dst

// ---------------------------------------------------------------- CSR build
__global__ void zero_deg_kernel() {
    int i = blockIdx.x * blockDim.x + threadIdx.x;
    if (i < N_NODES) g_deg[i] = 0;
}

__global__ void hist_kernel(const int* __restrict__ ei) {
    int e = blockIdx.x * blockDim.x + threadIdx.x;
    if (e >= N_EDGES) return;
    atomicAdd(&g_deg[__ldg(ei + N_EDGES + e)], 1);
}

// per-1024-block inclusive scan (Hillis-Steele) -> local exclusive + block sum
__global__ void scan_block_kernel() {
    __shared__ int sh[1024];
    int t = threadIdx.x;
    int i = blockIdx.x * 1024 + t;
    int v = (i < N_NODES) ? g_deg[i] : 0;
    sh[t] = v;
    __syncthreads();
    #pragma unroll
    for (int o = 1; o < 1024; o <<= 1) {
        int u = (t >= o) ? sh[t - o] : 0;
        __syncthreads();
        sh[t] += u;
        __syncthreads();
    }
    if (i < N_NODES) g_excl[i] = sh[t] - v;
    if (t == 1023) g_bsum[blockIdx.x] = sh[1023];
}

__global__ void scan_bsum_kernel() {
    if (threadIdx.x == 0 && blockIdx.x == 0) {
        int acc = 0;
        for (int b = 0; b < NB_SCAN; b++) { g_boff[b] = acc; acc += g_bsum[b]; }
        g_ptr[N_NODES] = acc;   // == N_EDGES
    }
}

__global__ void finalize_ptr_kernel() {
    int i = blockIdx.x * blockDim.x + threadIdx.x;
    if (i >= N_NODES) return;
    int p = g_excl[i] + g_boff[i >> 10];
    g_ptr[i] = p;
    g_pos[i] = p;
}

__global__ void scatter_kernel(const int* __restrict__ ei) {
    int e = blockIdx.x * blockDim.x + threadIdx.x;
    if (e >= N_EDGES) return;
    int s = __ldg(ei + e);
    int d = __ldg(ei + N_EDGES + e);
    int p = atomicAdd(&g_pos[d], 1);
    g_csr[p] = s;
}

// ---------------------------------------------------------------- GEMM1
// y1[n][0:64] = x[n] @ W1_l ; y1[n][64:128] = x[n] @ W1_r.
// BM=64, BN=128, K=128. 256 threads, TM=8 x TN=4 register tile.
__global__ void gemm1_kernel(const float* __restrict__ x,
                             const float* __restrict__ Wl,
                             const float* __restrict__ Wr) {
    __shared__ float As[64][128];  // 32 KB
    const int bm = blockIdx.x * 64;
    const int t  = threadIdx.x;

    for (int i = t; i < 64 * 32; i += 256) {
        int m = i >> 5, k4 = i & 31;
        int gm = bm + m;
        float4 v = make_float4(0.f, 0.f, 0.f, 0.f);
        if (gm < N_NODES) v = __ldg((const float4*)x + gm * 32 + k4);
        *(float4*)&As[m][k4 * 4] = v;
    }
    __syncthreads();

    const int ng = t & 31, mg = t >> 5;
    const int n0 = ng * 4, m0 = mg * 8;
    const float* B = (n0 < 64) ? (Wl + n0) : (Wr + (n0 - 64));

    float acc[8][4];
    #pragma unroll
    for (int i = 0; i < 8; i++)
        { acc[i][0] = 0.f; acc[i][1] = 0.f; acc[i][2] = 0.f; acc[i][3] = 0.f; }

    #pragma unroll 4
    for (int k = 0; k < 128; k++) {
        float4 b = __ldg((const float4*)(B + k * 64));
        #pragma unroll
        for (int i = 0; i < 8; i++) {
            float a = As[m0 + i][k];
            acc[i][0] += a * b.x; acc[i][1] += a * b.y;
            acc[i][2] += a * b.z; acc[i][3] += a * b.w;
        }
    }

    #pragma unroll
    for (int i = 0; i < 8; i++) {
        int gm = bm + m0 + i;
        if (gm < N_NODES)
            *(float4*)&g_y1[gm * 128 + n0] =
                make_float4(acc[i][0], acc[i][1], acc[i][2], acc[i][3]);
    }
}

// ---------------------------------------------------------------- agg1 (fused mean-agg + self + bias + relu)
// 16 threads per node; thread j owns float4 chunk j of the 64-f l-part.
__global__ void agg1_kernel(const float* __restrict__ b1) {
    int g = (blockIdx.x * blockDim.x + threadIdx.x) >> 4;
    int j = threadIdx.x & 15;
    if (g >= N_NODES) return;

    int beg = __ldg(&g_ptr[g]), end = __ldg(&g_ptr[g + 1]);
    float4 acc = make_float4(0.f, 0.f, 0.f, 0.f);

    int k = beg;
    for (; k + 4 <= end; k += 4) {   // unroll-4 for MLP
        int s0 = __ldg(&g_csr[k]);
        int s1 = __ldg(&g_csr[k + 1]);
        int s2 = __ldg(&g_csr[k + 2]);
        int s3 = __ldg(&g_csr[k + 3]);
        float4 v0 = __ldg((const float4*)g_y1 + s0 * 32 + j);
        float4 v1 = __ldg((const float4*)g_y1 + s1 * 32 + j);
        float4 v2 = __ldg((const float4*)g_y1 + s2 * 32 + j);
        float4 v3 = __ldg((const float4*)g_y1 + s3 * 32 + j);
        acc.x += v0.x + v1.x + v2.x + v3.x;
        acc.y += v0.y + v1.y + v2.y + v3.y;
        acc.z += v0.z + v1.z + v2.z + v3.z;
        acc.w += v0.w + v1.w + v2.w + v3.w;
    }
    for (; k < end; k++) {
        int s = __ldg(&g_csr[k]);
        float4 v = __ldg((const float4*)g_y1 + s * 32 + j);
        acc.x += v.x; acc.y += v.y; acc.z += v.z; acc.w += v.w;
    }

    float inv = 1.0f / fmaxf((float)(end - beg), 1.0f);
    float4 self = __ldg((const float4*)g_y1 + g * 32 + 16 + j);  // r-part
    float4 bb   = __ldg((const float4*)b1 + j);
    float4 h;
    h.x = fmaxf(acc.x * inv + self.x + bb.x, 0.f);
    h.y = fmaxf(acc.y * inv + self.y + bb.y, 0.f);
    h.z = fmaxf(acc.z * inv + self.z + bb.z, 0.f);
    h.w = fmaxf(acc.w * inv + self.w + bb.w, 0.f);
    *((float4*)g_h + g * 16 + j) = h;
}

// ---------------------------------------------------------------- GEMM2
// y2[n][0:40] = h[n] @ W2_l ; y2[n][40:80] = h[n] @ W2_r. BM=64, BN=80, K=64.
__global__ void gemm2_kernel(const float* __restrict__ Wl,
                             const float* __restrict__ Wr) {
    __shared__ float As[64][64];  // 16 KB
    const int bm = blockIdx.x * 64;
    const int t  = threadIdx.x;

    for (int i = t; i < 64 * 16; i += 160) {
        int m = i >> 4, k4 = i & 15;
        int gm = bm + m;
        float4 v = make_float4(0.f, 0.f, 0.f, 0.f);
        if (gm < N_NODES) v = *((const float4*)g_h + gm * 16 + k4);
        *(float4*)&As[m][k4 * 4] = v;
    }
    __syncthreads();

    const int ng = t % 20, mg = t / 20;
    const int n0 = ng * 4, m0 = mg * 8;
    const float* B = (n0 < 40) ? (Wl + n0) : (Wr + (n0 - 40));

    float acc[8][4];
    #pragma unroll
    for (int i = 0; i < 8; i++)
        { acc[i][0] = 0.f; acc[i][1] = 0.f; acc[i][2] = 0.f; acc[i][3] = 0.f; }

    #pragma unroll 4
    for (int k = 0; k < 64; k++) {
        float4 b = __ldg((const float4*)(B + k * 40));
        #pragma unroll
        for (int i = 0; i < 8; i++) {
            float a = As[m0 + i][k];
            acc[i][0] += a * b.x; acc[i][1] += a * b.y;
            acc[i][2] += a * b.z; acc[i][3] += a * b.w;
        }
    }

    #pragma unroll
    for (int i = 0; i < 8; i++) {
        int gm = bm + m0 + i;
        if (gm < N_NODES)
            *(float4*)&g_y2[gm * 80 + n0] =
                make_float4(acc[i][0], acc[i][1], acc[i][2], acc[i][3]);
    }
}

// ---------------------------------------------------------------- agg2 + log_softmax (fused)
// one warp per node; lanes 0..9 own float4 chunks of the 40-f z-part.
__global__ void agg2_kernel(const float* __restrict__ b2, float* __restrict__ out) {
    int n    = (blockIdx.x * blockDim.x + threadIdx.x) >> 5;
    int lane = threadIdx.x & 31;
    if (n >= N_NODES) return;

    int beg = __ldg(&g_ptr[n]), end = __ldg(&g_ptr[n + 1]);
    bool act = lane < 10;
    float4 acc = make_float4(0.f, 0.f, 0.f, 0.f);

    int k = beg;
    for (; k + 4 <= end; k += 4) {
        int s0 = __ldg(&g_csr[k]);
        int s1 = __ldg(&g_csr[k + 1]);
        int s2 = __ldg(&g_csr[k + 2]);
        int s3 = __ldg(&g_csr[k + 3]);
        if (act) {
            float4 v0 = __ldg((const float4*)g_y2 + s0 * 20 + lane);
            float4 v1 = __ldg((const float4*)g_y2 + s1 * 20 + lane);
            float4 v2 = __ldg((const float4*)g_y2 + s2 * 20 + lane);
            float4 v3 = __ldg((const float4*)g_y2 + s3 * 20 + lane);
            acc.x += v0.x + v1.x + v2.x + v3.x;
            acc.y += v0.y + v1.y + v2.y + v3.y;
            acc.z += v0.z + v1.z + v2.z + v3.z;
            acc.w += v0.w + v1.w + v2.w + v3.w;
        }
    }
    for (; k < end; k++) {
        int s = __ldg(&g_csr[k]);
        if (act) {
            float4 v = __ldg((const float4*)g_y2 + s * 20 + lane);
            acc.x += v.x; acc.y += v.y; acc.z += v.z; acc.w += v.w;
        }
    }

    float inv = 1.0f / fmaxf((float)(end - beg), 1.0f);
    float4 v = make_float4(-3.0e38f, -3.0e38f, -3.0e38f, -3.0e38f);
    if (act) {
        float4 self = __ldg((const float4*)g_y2 + n * 20 + 10 + lane);  // r-part
        float4 bb   = __ldg((const float4*)b2 + lane);
        v.x = acc.x * inv + self.x + bb.x;
        v.y = acc.y * inv + self.y + bb.y;
        v.z = acc.z * inv + self.z + bb.z;
        v.w = acc.w * inv + self.w + bb.w;
    }

    float m = fmaxf(fmaxf(v.x, v.y), fmaxf(v.z, v.w));
    #pragma unroll
    for (int o = 16; o; o >>= 1) m = fmaxf(m, __shfl_xor_sync(0xFFFFFFFFu, m, o));

    float s = act ? (expf(v.x - m) + expf(v.y - m) + expf(v.z - m) + expf(v.w - m)) : 0.f;
    #pragma unroll
    for (int o = 16; o; o >>= 1) s += __shfl_xor_sync(0xFFFFFFFFu, s, o);

    float lse = m + logf(s);
    if (act)
        *((float4*)out + n * 10 + lane) =
            make_float4(v.x - lse, v.y - lse, v.z - lse, v.w - lse);
}

// ---------------------------------------------------------------- launch
// Inputs resolved BY ELEMENT COUNT (robust to metadata ordering).
extern "C" void kernel_launch(void* const* d_in, const int* in_sizes, int n_in,
                              void* d_out, int out_size) {
    const float* x   = 0; const int* ei = 0;
    const float* W1l = 0; const float* W1r = 0; const float* b1 = 0;
    const float* W2l = 0; const float* W2r = 0; const float* b2 = 0;

    for (int i = 0; i < n_in; i++) {
        int sz = in_sizes[i];
        const void* p = d_in[i];
        if      (sz == N_NODES * 128)  x  = (const float*)p;
        else if (sz == 2 * N_EDGES)    ei = (const int*)p;
        else if (sz == 128 * 64) { if (!W1l) W1l = (const float*)p; else W1r = (const float*)p; }
        else if (sz == 64 * 40)  { if (!W2l) W2l = (const float*)p; else W2r = (const float*)p; }
        else if (sz == 64)             b1 = (const float*)p;
        else if (sz == 40)             b2 = (const float*)p;
    }
    float* out = (float*)d_out;

    // CSR build
    zero_deg_kernel    <<<(N_NODES + 255) / 256, 256>>>();
    hist_kernel        <<<(N_EDGES + 255) / 256, 256>>>(ei);
    scan_block_kernel  <<<NB_SCAN, 1024>>>();
    scan_bsum_kernel   <<<1, 32>>>();
    finalize_ptr_kernel<<<(N_NODES + 255) / 256, 256>>>();
    scatter_kernel     <<<(N_EDGES + 255) / 256, 256>>>(ei);

    // layer 1
    gemm1_kernel<<<(N_NODES + 63) / 64, 256>>>(x, W1l, W1r);
    agg1_kernel <<<(N_NODES * 16 + 255) / 256, 256>>>(b1);

    // layer 2 + softmax
    gemm2_kernel<<<(N_NODES + 63) / 64, 160>>>(W2l, W2r);
    agg2_kernel <<<(N_NODES * 32 + 255) / 256, 256>>>(b2, out);
}

// round 7
// speedup vs baseline: 2.0999x; 1.0363x over previous
#include <cuda_runtime.h>

#define N_NODES 100000
#define N_EDGES 1600000
#define NB_SCAN 98            // ceil(100000/1024)
// layer dims: F_IN=128, HID=64, N_CLS=40

// Scratch (device globals: allocation-free, graph-safe)
__device__ __align__(16) float g_y1[N_NODES * 128];   // [x@W1_l | x@W1_r]
__device__ __align__(16) float g_h[N_NODES * 64];     // relu output
__device__ __align__(16) float g_y2[N_NODES * 80];    // [h@W2_l | h@W2_r]
__device__ int g_deg[N_NODES];        // in-degree histogram
__device__ int g_excl[N_NODES];       // block-local exclusive scan
__device__ int g_bsum[NB_SCAN];       // per-block sums
__device__ int g_boff[NB_SCAN];       // scanned block offsets
__device__ int g_ptr[N_NODES + 1];    // CSR row pointers (by dst)
__device__ int g_pos[N_NODES];        // scatter cursors
__device__ int g_csr[N_EDGES];        // src ids grouped by dst

// ---------------------------------------------------------------- f32x2 helpers
__device__ __forceinline__ unsigned long long pk2(float lo, float hi) {
    unsigned long long r;
    asm("mov.b64 %0, {%1, %2};" : "=l"(r) : "f"(lo), "f"(hi));
    return r;
}
__device__ __forceinline__ void fma2(unsigned long long& d,
                                     unsigned long long a, unsigned long long b) {
    asm("fma.rn.f32x2 %0, %1, %2, %0;" : "+l"(d) : "l"(a), "l"(b));
}
__device__ __forceinline__ float sum2(unsigned long long v) {
    float lo, hi;
    asm("mov.b64 {%0, %1}, %2;" : "=f"(lo), "=f"(hi) : "l"(v));
    return lo + hi;
}

// ---------------------------------------------------------------- CSR build
__global__ void zero_deg_kernel() {
    int i = blockIdx.x * blockDim.x + threadIdx.x;
    if (i < N_NODES) g_deg[i] = 0;
}

__global__ void hist_kernel(const int* __restrict__ ei) {
    int e = blockIdx.x * blockDim.x + threadIdx.x;
    if (e >= N_EDGES) return;
    atomicAdd(&g_deg[__ldg(ei + N_EDGES + e)], 1);
}

// per-1024-block inclusive scan (Hillis-Steele) -> local exclusive + block sum
__global__ void scan_block_kernel() {
    __shared__ int sh[1024];
    int t = threadIdx.x;
    int i = blockIdx.x * 1024 + t;
    int v = (i < N_NODES) ? g_deg[i] : 0;
    sh[t] = v;
    __syncthreads();
    #pragma unroll
    for (int o = 1; o < 1024; o <<= 1) {
        int u = (t >= o) ? sh[t - o] : 0;
        __syncthreads();
        sh[t] += u;
        __syncthreads();
    }
    if (i < N_NODES) g_excl[i] = sh[t] - v;
    if (t == 1023) g_bsum[blockIdx.x] = sh[1023];
}

// parallel exclusive scan of the 98 block sums (1 block, 128 threads)
__global__ void scan_bsum_kernel() {
    __shared__ int sh[128];
    int t = threadIdx.x;
    int v = (t < NB_SCAN) ? g_bsum[t] : 0;
    sh[t] = v;
    __syncthreads();
    #pragma unroll
    for (int o = 1; o < 128; o <<= 1) {
        int u = (t >= o) ? sh[t - o] : 0;
        __syncthreads();
        sh[t] += u;
        __syncthreads();
    }
    if (t < NB_SCAN) g_boff[t] = sh[t] - v;
    if (t == 127) g_ptr[N_NODES] = sh[127];   // == N_EDGES
}

__global__ void finalize_ptr_kernel() {
    int i = blockIdx.x * blockDim.x + threadIdx.x;
    if (i >= N_NODES) return;
    int p = g_excl[i] + g_boff[i >> 10];
    g_ptr[i] = p;
    g_pos[i] = p;
}

__global__ void scatter_kernel(const int* __restrict__ ei) {
    int e = blockIdx.x * blockDim.x + threadIdx.x;
    if (e >= N_EDGES) return;
    int s = __ldg(ei + e);
    int d = __ldg(ei + N_EDGES + e);
    int p = atomicAdd(&g_pos[d], 1);
    g_csr[p] = s;
}

// ---------------------------------------------------------------- GEMM1 (FFMA2, K-paired)
// y1[n][0:64] = x[n] @ W1_l ; y1[n][64:128] = x[n] @ W1_r.
// BM=64, BN=128, K=128. 256 threads, TM=8 x TN=4 register tile.
// acc[i][c] is f32x2 (even-k partial, odd-k partial); summed in epilogue.
__global__ void gemm1_kernel(const float* __restrict__ x,
                             const float* __restrict__ Wl,
                             const float* __restrict__ Wr) {
    __shared__ float As[64][128];  // 32 KB
    const int bm = blockIdx.x * 64;
    const int t  = threadIdx.x;

    for (int i = t; i < 64 * 32; i += 256) {
        int m = i >> 5, k4 = i & 31;
        int gm = bm + m;
        float4 v = make_float4(0.f, 0.f, 0.f, 0.f);
        if (gm < N_NODES) v = __ldg((const float4*)x + gm * 32 + k4);
        *(float4*)&As[m][k4 * 4] = v;
    }
    __syncthreads();

    const int ng = t & 31, mg = t >> 5;
    const int n0 = ng * 4, m0 = mg * 8;
    const float* B = (n0 < 64) ? (Wl + n0) : (Wr + (n0 - 64));

    unsigned long long acc[8][4];
    #pragma unroll
    for (int i = 0; i < 8; i++)
        { acc[i][0] = 0ull; acc[i][1] = 0ull; acc[i][2] = 0ull; acc[i][3] = 0ull; }

    #pragma unroll 4
    for (int k = 0; k < 128; k += 2) {
        float4 b0 = __ldg((const float4*)(B + k * 64));
        float4 b1 = __ldg((const float4*)(B + (k + 1) * 64));
        unsigned long long bx = pk2(b0.x, b1.x);
        unsigned long long by = pk2(b0.y, b1.y);
        unsigned long long bz = pk2(b0.z, b1.z);
        unsigned long long bw = pk2(b0.w, b1.w);
        #pragma unroll
        for (int i = 0; i < 8; i++) {
            float2 a = *(const float2*)&As[m0 + i][k];   // LDS.64, lane-uniform broadcast
            unsigned long long ap = pk2(a.x, a.y);
            fma2(acc[i][0], ap, bx);
            fma2(acc[i][1], ap, by);
            fma2(acc[i][2], ap, bz);
            fma2(acc[i][3], ap, bw);
        }
    }

    #pragma unroll
    for (int i = 0; i < 8; i++) {
        int gm = bm + m0 + i;
        if (gm < N_NODES)
            *(float4*)&g_y1[gm * 128 + n0] =
                make_float4(sum2(acc[i][0]), sum2(acc[i][1]),
                            sum2(acc[i][2]), sum2(acc[i][3]));
    }
}

// ---------------------------------------------------------------- agg1 (fused mean-agg + self + bias + relu)
// 16 threads per node; thread j owns float4 chunk j of the 64-f l-part.
__global__ void agg1_kernel(const float* __restrict__ b1) {
    int g = (blockIdx.x * blockDim.x + threadIdx.x) >> 4;
    int j = threadIdx.x & 15;
    if (g >= N_NODES) return;

    int beg = __ldg(&g_ptr[g]), end = __ldg(&g_ptr[g + 1]);
    float4 acc = make_float4(0.f, 0.f, 0.f, 0.f);

    int k = beg;
    for (; k + 4 <= end; k += 4) {
        int s0 = __ldg(&g_csr[k]);
        int s1 = __ldg(&g_csr[k + 1]);
        int s2 = __ldg(&g_csr[k + 2]);
        int s3 = __ldg(&g_csr[k + 3]);
        float4 v0 = __ldg((const float4*)g_y1 + s0 * 32 + j);
        float4 v1 = __ldg((const float4*)g_y1 + s1 * 32 + j);
        float4 v2 = __ldg((const float4*)g_y1 + s2 * 32 + j);
        float4 v3 = __ldg((const float4*)g_y1 + s3 * 32 + j);
        acc.x += v0.x + v1.x + v2.x + v3.x;
        acc.y += v0.y + v1.y + v2.y + v3.y;
        acc.z += v0.z + v1.z + v2.z + v3.z;
        acc.w += v0.w + v1.w + v2.w + v3.w;
    }
    for (; k < end; k++) {
        int s = __ldg(&g_csr[k]);
        float4 v = __ldg((const float4*)g_y1 + s * 32 + j);
        acc.x += v.x; acc.y += v.y; acc.z += v.z; acc.w += v.w;
    }

    float inv = 1.0f / fmaxf((float)(end - beg), 1.0f);
    float4 self = __ldg((const float4*)g_y1 + g * 32 + 16 + j);  // r-part
    float4 bb   = __ldg((const float4*)b1 + j);
    float4 h;
    h.x = fmaxf(acc.x * inv + self.x + bb.x, 0.f);
    h.y = fmaxf(acc.y * inv + self.y + bb.y, 0.f);
    h.z = fmaxf(acc.z * inv + self.z + bb.z, 0.f);
    h.w = fmaxf(acc.w * inv + self.w + bb.w, 0.f);
    *((float4*)g_h + g * 16 + j) = h;
}

// ---------------------------------------------------------------- GEMM2 (FFMA2, K-paired)
// y2[n][0:40] = h[n] @ W2_l ; y2[n][40:80] = h[n] @ W2_r. BM=64, BN=80, K=64.
// 160 threads: 20 col-groups (TN=4) x 8 row-groups (TM=8).
__global__ void gemm2_kernel(const float* __restrict__ Wl,
                             const float* __restrict__ Wr) {
    __shared__ float As[64][64];  // 16 KB
    const int bm = blockIdx.x * 64;
    const int t  = threadIdx.x;

    for (int i = t; i < 64 * 16; i += 160) {
        int m = i >> 4, k4 = i & 15;
        int gm = bm + m;
        float4 v = make_float4(0.f, 0.f, 0.f, 0.f);
        if (gm < N_NODES) v = *((const float4*)g_h + gm * 16 + k4);
        *(float4*)&As[m][k4 * 4] = v;
    }
    __syncthreads();

    const int ng = t % 20, mg = t / 20;
    const int n0 = ng * 4, m0 = mg * 8;
    const float* B = (n0 < 40) ? (Wl + n0) : (Wr + (n0 - 40));

    unsigned long long acc[8][4];
    #pragma unroll
    for (int i = 0; i < 8; i++)
        { acc[i][0] = 0ull; acc[i][1] = 0ull; acc[i][2] = 0ull; acc[i][3] = 0ull; }

    #pragma unroll 4
    for (int k = 0; k < 64; k += 2) {
        float4 b0 = __ldg((const float4*)(B + k * 40));
        float4 b1 = __ldg((const float4*)(B + (k + 1) * 40));
        unsigned long long bx = pk2(b0.x, b1.x);
        unsigned long long by = pk2(b0.y, b1.y);
        unsigned long long bz = pk2(b0.z, b1.z);
        unsigned long long bw = pk2(b0.w, b1.w);
        #pragma unroll
        for (int i = 0; i < 8; i++) {
            float2 a = *(const float2*)&As[m0 + i][k];
            unsigned long long ap = pk2(a.x, a.y);
            fma2(acc[i][0], ap, bx);
            fma2(acc[i][1], ap, by);
            fma2(acc[i][2], ap, bz);
            fma2(acc[i][3], ap, bw);
        }
    }

    #pragma unroll
    for (int i = 0; i < 8; i++) {
        int gm = bm + m0 + i;
        if (gm < N_NODES)
            *(float4*)&g_y2[gm * 80 + n0] =
                make_float4(sum2(acc[i][0]), sum2(acc[i][1]),
                            sum2(acc[i][2]), sum2(acc[i][3]));
    }
}

// ---------------------------------------------------------------- agg2 + log_softmax (fused)
// one warp per node; lanes 0..9 own float4 chunks of the 40-f z-part.
__global__ void agg2_kernel(const float* __restrict__ b2, float* __restrict__ out) {
    int n    = (blockIdx.x * blockDim.x + threadIdx.x) >> 5;
    int lane = threadIdx.x & 31;
    if (n >= N_NODES) return;

    int beg = __ldg(&g_ptr[n]), end = __ldg(&g_ptr[n + 1]);
    bool act = lane < 10;
    float4 acc = make_float4(0.f, 0.f, 0.f, 0.f);

    int k = beg;
    for (; k + 4 <= end; k += 4) {
        int s0 = __ldg(&g_csr[k]);
        int s1 = __ldg(&g_csr[k + 1]);
        int s2 = __ldg(&g_csr[k + 2]);
        int s3 = __ldg(&g_csr[k + 3]);
        if (act) {
            float4 v0 = __ldg((const float4*)g_y2 + s0 * 20 + lane);
            float4 v1 = __ldg((const float4*)g_y2 + s1 * 20 + lane);
            float4 v2 = __ldg((const float4*)g_y2 + s2 * 20 + lane);
            float4 v3 = __ldg((const float4*)g_y2 + s3 * 20 + lane);
            acc.x += v0.x + v1.x + v2.x + v3.x;
            acc.y += v0.y + v1.y + v2.y + v3.y;
            acc.z += v0.z + v1.z + v2.z + v3.z;
            acc.w += v0.w + v1.w + v2.w + v3.w;
        }
    }
    for (; k < end; k++) {
        int s = __ldg(&g_csr[k]);
        if (act) {
            float4 v = __ldg((const float4*)g_y2 + s * 20 + lane);
            acc.x += v.x; acc.y += v.y; acc.z += v.z; acc.w += v.w;
        }
    }

    float inv = 1.0f / fmaxf((float)(end - beg), 1.0f);
    float4 v = make_float4(-3.0e38f, -3.0e38f, -3.0e38f, -3.0e38f);
    if (act) {
        float4 self = __ldg((const float4*)g_y2 + n * 20 + 10 + lane);  // r-part
        float4 bb   = __ldg((const float4*)b2 + lane);
        v.x = acc.x * inv + self.x + bb.x;
        v.y = acc.y * inv + self.y + bb.y;
        v.z = acc.z * inv + self.z + bb.z;
        v.w = acc.w * inv + self.w + bb.w;
    }

    float m = fmaxf(fmaxf(v.x, v.y), fmaxf(v.z, v.w));
    #pragma unroll
    for (int o = 16; o; o >>= 1) m = fmaxf(m, __shfl_xor_sync(0xFFFFFFFFu, m, o));

    float s = act ? (expf(v.x - m) + expf(v.y - m) + expf(v.z - m) + expf(v.w - m)) : 0.f;
    #pragma unroll
    for (int o = 16; o; o >>= 1) s += __shfl_xor_sync(0xFFFFFFFFu, s, o);

    float lse = m + logf(s);
    if (act)
        *((float4*)out + n * 10 + lane) =
            make_float4(v.x - lse, v.y - lse, v.z - lse, v.w - lse);
}

// ---------------------------------------------------------------- launch
// Inputs resolved BY ELEMENT COUNT (robust to metadata ordering).
extern "C" void kernel_launch(void* const* d_in, const int* in_sizes, int n_in,
                              void* d_out, int out_size) {
    const float* x   = 0; const int* ei = 0;
    const float* W1l = 0; const float* W1r = 0; const float* b1 = 0;
    const float* W2l = 0; const float* W2r = 0; const float* b2 = 0;

    for (int i = 0; i < n_in; i++) {
        int sz = in_sizes[i];
        const void* p = d_in[i];
        if      (sz == N_NODES * 128)  x  = (const float*)p;
        else if (sz == 2 * N_EDGES)    ei = (const int*)p;
        else if (sz == 128 * 64) { if (!W1l) W1l = (const float*)p; else W1r = (const float*)p; }
        else if (sz == 64 * 40)  { if (!W2l) W2l = (const float*)p; else W2r = (const float*)p; }
        else if (sz == 64)             b1 = (const float*)p;
        else if (sz == 40)             b2 = (const float*)p;
    }
    float* out = (float*)d_out;

    // CSR build
    zero_deg_kernel    <<<(N_NODES + 255) / 256, 256>>>();
    hist_kernel        <<<(N_EDGES + 255) / 256, 256>>>(ei);
    scan_block_kernel  <<<NB_SCAN, 1024>>>();
    scan_bsum_kernel   <<<1, 128>>>();
    finalize_ptr_kernel<<<(N_NODES + 255) / 256, 256>>>();
    scatter_kernel     <<<(N_EDGES + 255) / 256, 256>>>(ei);

    // layer 1
    gemm1_kernel<<<(N_NODES + 63) / 64, 256>>>(x, W1l, W1r);
    agg1_kernel <<<(N_NODES * 16 + 255) / 256, 256>>>(b1);

    // layer 2 + softmax
    gemm2_kernel<<<(N_NODES + 63) / 64, 160>>>(W2l, W2r);
    agg2_kernel <<<(N_NODES * 32 + 255) / 256, 256>>>(b2, out);
}

// round 8
// speedup vs baseline: 2.2168x; 1.0557x over previous
#include <cuda_runtime.h>

#define N_NODES 100000
#define N_EDGES 1600000
#define NB_SCAN 98            // ceil(100000/1024)
// layer dims: F_IN=128, HID=64, N_CLS=40

// Scratch (device globals: allocation-free, graph-safe)
__device__ __align__(16) float g_y1[N_NODES * 128];   // [x@W1_l | x@W1_r]
__device__ __align__(16) float g_h[N_NODES * 64];     // relu output
__device__ __align__(16) float g_y2[N_NODES * 80];    // [h@W2_l | h@W2_r]
__device__ int g_deg[N_NODES];        // in-degree histogram
__device__ int g_excl[N_NODES];       // block-local exclusive scan
__device__ int g_bsum[NB_SCAN];       // per-block sums
__device__ int g_boff[NB_SCAN];       // scanned block offsets
__device__ int g_ptr[N_NODES + 1];    // CSR row pointers (by dst)
__device__ int g_pos[N_NODES];        // scatter cursors
__device__ int g_csr[N_EDGES];        // src ids grouped by dst

// ---------------------------------------------------------------- f32x2 helpers
__device__ __forceinline__ unsigned long long pk2(float lo, float hi) {
    unsigned long long r;
    asm("mov.b64 %0, {%1, %2};" : "=l"(r) : "f"(lo), "f"(hi));
    return r;
}
__device__ __forceinline__ void fma2(unsigned long long& d,
                                     unsigned long long a, unsigned long long b) {
    asm("fma.rn.f32x2 %0, %1, %2, %0;" : "+l"(d) : "l"(a), "l"(b));
}
__device__ __forceinline__ float sum2(unsigned long long v) {
    float lo, hi;
    asm("mov.b64 {%0, %1}, %2;" : "=f"(lo), "=f"(hi) : "l"(v));
    return lo + hi;
}

// ---------------------------------------------------------------- CSR build
__global__ void zero_deg_kernel() {
    int i = blockIdx.x * blockDim.x + threadIdx.x;
    if (i < N_NODES) g_deg[i] = 0;
}

__global__ void hist_kernel(const int* __restrict__ ei) {
    int e = blockIdx.x * blockDim.x + threadIdx.x;
    if (e >= N_EDGES) return;
    atomicAdd(&g_deg[__ldg(ei + N_EDGES + e)], 1);
}

// warp-shuffle block scan (1024 threads): local exclusive + block sum
__global__ void scan_block_kernel() {
    __shared__ int wsum[32];
    int t = threadIdx.x;
    int i = blockIdx.x * 1024 + t;
    int v = (i < N_NODES) ? g_deg[i] : 0;
    int lane = t & 31, w = t >> 5;

    int incl = v;
    #pragma unroll
    for (int o = 1; o < 32; o <<= 1) {
        int u = __shfl_up_sync(0xFFFFFFFFu, incl, o);
        if (lane >= o) incl += u;
    }
    if (lane == 31) wsum[w] = incl;
    __syncthreads();
    if (w == 0) {
        int s = wsum[lane];
        #pragma unroll
        for (int o = 1; o < 32; o <<= 1) {
            int u = __shfl_up_sync(0xFFFFFFFFu, s, o);
            if (lane >= o) s += u;
        }
        wsum[lane] = s;
    }
    __syncthreads();
    int off = (w > 0) ? wsum[w - 1] : 0;
    incl += off;
    if (i < N_NODES) g_excl[i] = incl - v;
    if (t == 1023) g_bsum[blockIdx.x] = incl;
}

// warp-shuffle scan of the 98 block sums (1 block, 128 threads)
__global__ void scan_bsum_kernel() {
    __shared__ int wsum[4];
    int t = threadIdx.x;
    int v = (t < NB_SCAN) ? g_bsum[t] : 0;
    int lane = t & 31, w = t >> 5;

    int incl = v;
    #pragma unroll
    for (int o = 1; o < 32; o <<= 1) {
        int u = __shfl_up_sync(0xFFFFFFFFu, incl, o);
        if (lane >= o) incl += u;
    }
    if (lane == 31) wsum[w] = incl;
    __syncthreads();
    if (t == 0) {
        int a = wsum[0];
        wsum[1] += a; a = wsum[1];
        wsum[2] += a; a = wsum[2];
        wsum[3] += a;
    }
    __syncthreads();
    int off = (w > 0) ? wsum[w - 1] : 0;
    incl += off;
    if (t < NB_SCAN) g_boff[t] = incl - v;
    if (t == 127) g_ptr[N_NODES] = incl;   // == N_EDGES
}

__global__ void finalize_ptr_kernel() {
    int i = blockIdx.x * blockDim.x + threadIdx.x;
    if (i >= N_NODES) return;
    int p = g_excl[i] + g_boff[i >> 10];
    g_ptr[i] = p;
    g_pos[i] = p;
}

__global__ void scatter_kernel(const int* __restrict__ ei) {
    int e = blockIdx.x * blockDim.x + threadIdx.x;
    if (e >= N_EDGES) return;
    int s = __ldg(ei + e);
    int d = __ldg(ei + N_EDGES + e);
    int p = atomicAdd(&g_pos[d], 1);
    g_csr[p] = s;
}

// ---------------------------------------------------------------- GEMM1 (FFMA2, K-paired)
__global__ void gemm1_kernel(const float* __restrict__ x,
                             const float* __restrict__ Wl,
                             const float* __restrict__ Wr) {
    __shared__ float As[64][128];  // 32 KB
    const int bm = blockIdx.x * 64;
    const int t  = threadIdx.x;

    for (int i = t; i < 64 * 32; i += 256) {
        int m = i >> 5, k4 = i & 31;
        int gm = bm + m;
        float4 v = make_float4(0.f, 0.f, 0.f, 0.f);
        if (gm < N_NODES) v = __ldg((const float4*)x + gm * 32 + k4);
        *(float4*)&As[m][k4 * 4] = v;
    }
    __syncthreads();

    const int ng = t & 31, mg = t >> 5;
    const int n0 = ng * 4, m0 = mg * 8;
    const float* B = (n0 < 64) ? (Wl + n0) : (Wr + (n0 - 64));

    unsigned long long acc[8][4];
    #pragma unroll
    for (int i = 0; i < 8; i++)
        { acc[i][0] = 0ull; acc[i][1] = 0ull; acc[i][2] = 0ull; acc[i][3] = 0ull; }

    #pragma unroll 4
    for (int k = 0; k < 128; k += 2) {
        float4 b0 = __ldg((const float4*)(B + k * 64));
        float4 b1 = __ldg((const float4*)(B + (k + 1) * 64));
        unsigned long long bx = pk2(b0.x, b1.x);
        unsigned long long by = pk2(b0.y, b1.y);
        unsigned long long bz = pk2(b0.z, b1.z);
        unsigned long long bw = pk2(b0.w, b1.w);
        #pragma unroll
        for (int i = 0; i < 8; i++) {
            float2 a = *(const float2*)&As[m0 + i][k];
            unsigned long long ap = pk2(a.x, a.y);
            fma2(acc[i][0], ap, bx);
            fma2(acc[i][1], ap, by);
            fma2(acc[i][2], ap, bz);
            fma2(acc[i][3], ap, bw);
        }
    }

    #pragma unroll
    for (int i = 0; i < 8; i++) {
        int gm = bm + m0 + i;
        if (gm < N_NODES)
            *(float4*)&g_y1[gm * 128 + n0] =
                make_float4(sum2(acc[i][0]), sum2(acc[i][1]),
                            sum2(acc[i][2]), sum2(acc[i][3]));
    }
}

// ---------------------------------------------------------------- agg1 (fused mean-agg + self + bias + relu)
__global__ void agg1_kernel(const float* __restrict__ b1) {
    int g = (blockIdx.x * blockDim.x + threadIdx.x) >> 4;
    int j = threadIdx.x & 15;
    if (g >= N_NODES) return;

    int beg = __ldg(&g_ptr[g]), end = __ldg(&g_ptr[g + 1]);
    float4 acc = make_float4(0.f, 0.f, 0.f, 0.f);

    int k = beg;
    for (; k + 4 <= end; k += 4) {
        int s0 = __ldg(&g_csr[k]);
        int s1 = __ldg(&g_csr[k + 1]);
        int s2 = __ldg(&g_csr[k + 2]);
        int s3 = __ldg(&g_csr[k + 3]);
        float4 v0 = __ldg((const float4*)g_y1 + s0 * 32 + j);
        float4 v1 = __ldg((const float4*)g_y1 + s1 * 32 + j);
        float4 v2 = __ldg((const float4*)g_y1 + s2 * 32 + j);
        float4 v3 = __ldg((const float4*)g_y1 + s3 * 32 + j);
        acc.x += v0.x + v1.x + v2.x + v3.x;
        acc.y += v0.y + v1.y + v2.y + v3.y;
        acc.z += v0.z + v1.z + v2.z + v3.z;
        acc.w += v0.w + v1.w + v2.w + v3.w;
    }
    for (; k < end; k++) {
        int s = __ldg(&g_csr[k]);
        float4 v = __ldg((const float4*)g_y1 + s * 32 + j);
        acc.x += v.x; acc.y += v.y; acc.z += v.z; acc.w += v.w;
    }

    float inv = 1.0f / fmaxf((float)(end - beg), 1.0f);
    float4 self = __ldg((const float4*)g_y1 + g * 32 + 16 + j);
    float4 bb   = __ldg((const float4*)b1 + j);
    float4 h;
    h.x = fmaxf(acc.x * inv + self.x + bb.x, 0.f);
    h.y = fmaxf(acc.y * inv + self.y + bb.y, 0.f);
    h.z = fmaxf(acc.z * inv + self.z + bb.z, 0.f);
    h.w = fmaxf(acc.w * inv + self.w + bb.w, 0.f);
    *((float4*)g_h + g * 16 + j) = h;
}

// ---------------------------------------------------------------- GEMM2 (FFMA2, K-paired)
__global__ void gemm2_kernel(const float* __restrict__ Wl,
                             const float* __restrict__ Wr) {
    __shared__ float As[64][64];  // 16 KB
    const int bm = blockIdx.x * 64;
    const int t  = threadIdx.x;

    for (int i = t; i < 64 * 16; i += 160) {
        int m = i >> 4, k4 = i & 15;
        int gm = bm + m;
        float4 v = make_float4(0.f, 0.f, 0.f, 0.f);
        if (gm < N_NODES) v = *((const float4*)g_h + gm * 16 + k4);
        *(float4*)&As[m][k4 * 4] = v;
    }
    __syncthreads();

    const int ng = t % 20, mg = t / 20;
    const int n0 = ng * 4, m0 = mg * 8;
    const float* B = (n0 < 40) ? (Wl + n0) : (Wr + (n0 - 40));

    unsigned long long acc[8][4];
    #pragma unroll
    for (int i = 0; i < 8; i++)
        { acc[i][0] = 0ull; acc[i][1] = 0ull; acc[i][2] = 0ull; acc[i][3] = 0ull; }

    #pragma unroll 4
    for (int k = 0; k < 64; k += 2) {
        float4 b0 = __ldg((const float4*)(B + k * 40));
        float4 b1 = __ldg((const float4*)(B + (k + 1) * 40));
        unsigned long long bx = pk2(b0.x, b1.x);
        unsigned long long by = pk2(b0.y, b1.y);
        unsigned long long bz = pk2(b0.z, b1.z);
        unsigned long long bw = pk2(b0.w, b1.w);
        #pragma unroll
        for (int i = 0; i < 8; i++) {
            float2 a = *(const float2*)&As[m0 + i][k];
            unsigned long long ap = pk2(a.x, a.y);
            fma2(acc[i][0], ap, bx);
            fma2(acc[i][1], ap, by);
            fma2(acc[i][2], ap, bz);
            fma2(acc[i][3], ap, bw);
        }
    }

    #pragma unroll
    for (int i = 0; i < 8; i++) {
        int gm = bm + m0 + i;
        if (gm < N_NODES)
            *(float4*)&g_y2[gm * 80 + n0] =
                make_float4(sum2(acc[i][0]), sum2(acc[i][1]),
                            sum2(acc[i][2]), sum2(acc[i][3]));
    }
}

// ---------------------------------------------------------------- agg2 + log_softmax (fused)
__global__ void agg2_kernel(const float* __restrict__ b2, float* __restrict__ out) {
    int n    = (blockIdx.x * blockDim.x + threadIdx.x) >> 5;
    int lane = threadIdx.x & 31;
    if (n >= N_NODES) return;

    int beg = __ldg(&g_ptr[n]), end = __ldg(&g_ptr[n + 1]);
    bool act = lane < 10;
    float4 acc = make_float4(0.f, 0.f, 0.f, 0.f);

    int k = beg;
    for (; k + 4 <= end; k += 4) {
        int s0 = __ldg(&g_csr[k]);
        int s1 = __ldg(&g_csr[k + 1]);
        int s2 = __ldg(&g_csr[k + 2]);
        int s3 = __ldg(&g_csr[k + 3]);
        if (act) {
            float4 v0 = __ldg((const float4*)g_y2 + s0 * 20 + lane);
            float4 v1 = __ldg((const float4*)g_y2 + s1 * 20 + lane);
            float4 v2 = __ldg((const float4*)g_y2 + s2 * 20 + lane);
            float4 v3 = __ldg((const float4*)g_y2 + s3 * 20 + lane);
            acc.x += v0.x + v1.x + v2.x + v3.x;
            acc.y += v0.y + v1.y + v2.y + v3.y;
            acc.z += v0.z + v1.z + v2.z + v3.z;
            acc.w += v0.w + v1.w + v2.w + v3.w;
        }
    }
    for (; k < end; k++) {
        int s = __ldg(&g_csr[k]);
        if (act) {
            float4 v = __ldg((const float4*)g_y2 + s * 20 + lane);
            acc.x += v.x; acc.y += v.y; acc.z += v.z; acc.w += v.w;
        }
    }

    float inv = 1.0f / fmaxf((float)(end - beg), 1.0f);
    float4 v = make_float4(-3.0e38f, -3.0e38f, -3.0e38f, -3.0e38f);
    if (act) {
        float4 self = __ldg((const float4*)g_y2 + n * 20 + 10 + lane);
        float4 bb   = __ldg((const float4*)b2 + lane);
        v.x = acc.x * inv + self.x + bb.x;
        v.y = acc.y * inv + self.y + bb.y;
        v.z = acc.z * inv + self.z + bb.z;
        v.w = acc.w * inv + self.w + bb.w;
    }

    float m = fmaxf(fmaxf(v.x, v.y), fmaxf(v.z, v.w));
    #pragma unroll
    for (int o = 16; o; o >>= 1) m = fmaxf(m, __shfl_xor_sync(0xFFFFFFFFu, m, o));

    float s = act ? (expf(v.x - m) + expf(v.y - m) + expf(v.z - m) + expf(v.w - m)) : 0.f;
    #pragma unroll
    for (int o = 16; o; o >>= 1) s += __shfl_xor_sync(0xFFFFFFFFu, s, o);

    float lse = m + logf(s);
    if (act)
        *((float4*)out + n * 10 + lane) =
            make_float4(v.x - lse, v.y - lse, v.z - lse, v.w - lse);
}

// ---------------------------------------------------------------- launch
// Two concurrent chains captured via event fork/join:
//   main stream : gemm1  (needs x, W1 only)
//   side stream : CSR build (needs edge_index only)
// join -> agg1 -> gemm2 -> agg2.
extern "C" void kernel_launch(void* const* d_in, const int* in_sizes, int n_in,
                              void* d_out, int out_size) {
    const float* x   = 0; const int* ei = 0;
    const float* W1l = 0; const float* W1r = 0; const float* b1 = 0;
    const float* W2l = 0; const float* W2r = 0; const float* b2 = 0;

    for (int i = 0; i < n_in; i++) {
        int sz = in_sizes[i];
        const void* p = d_in[i];
        if      (sz == N_NODES * 128)  x  = (const float*)p;
        else if (sz == 2 * N_EDGES)    ei = (const int*)p;
        else if (sz == 128 * 64) { if (!W1l) W1l = (const float*)p; else W1r = (const float*)p; }
        else if (sz == 64 * 40)  { if (!W2l) W2l = (const float*)p; else W2r = (const float*)p; }
        else if (sz == 64)             b1 = (const float*)p;
        else if (sz == 40)             b2 = (const float*)p;
    }
    float* out = (float*)d_out;

    // Fork a side stream for the CSR chain. Created fresh per call and
    // intentionally not destroyed (kernel_launch runs twice total; destroying
    // a stream that participated in an active capture is illegal).
    cudaStream_t s1;
    cudaEvent_t evFork, evJoin;
    cudaStreamCreateWithFlags(&s1, cudaStreamNonBlocking);
    cudaEventCreateWithFlags(&evFork, cudaEventDisableTiming);
    cudaEventCreateWithFlags(&evJoin, cudaEventDisableTiming);

    cudaEventRecord(evFork, 0);
    cudaStreamWaitEvent(s1, evFork, 0);

    // side stream: CSR build
    zero_deg_kernel    <<<(N_NODES + 255) / 256, 256, 0, s1>>>();
    hist_kernel        <<<(N_EDGES + 255) / 256, 256, 0, s1>>>(ei);
    scan_block_kernel  <<<NB_SCAN, 1024, 0, s1>>>();
    scan_bsum_kernel   <<<1, 128, 0, s1>>>();
    finalize_ptr_kernel<<<(N_NODES + 255) / 256, 256, 0, s1>>>();
    scatter_kernel     <<<(N_EDGES + 255) / 256, 256, 0, s1>>>(ei);
    cudaEventRecord(evJoin, s1);

    // main stream: gemm1 runs concurrently with the CSR chain
    gemm1_kernel<<<(N_NODES + 63) / 64, 256>>>(x, W1l, W1r);

    // join, then the dependent tail
    cudaStreamWaitEvent(0, evJoin, 0);
    agg1_kernel <<<(N_NODES * 16 + 255) / 256, 256>>>(b1);
    gemm2_kernel<<<(N_NODES + 63) / 64, 160>>>(W2l, W2r);
    agg2_kernel <<<(N_NODES * 32 + 255) / 256, 256>>>(b2, out);
}